// round 16
// baseline (speedup 1.0000x reference)
#include <cuda_runtime.h>

#define HH 480
#define WW 640
#define NC 3
#define SKIP 5
#define PH 96            // HH/SKIP
#define PW 128           // WW/SKIP
#define NP (PH*PW)       // 12288 sampled pixels
#define BH 60            // bin rows   (GRID=8, start 4)
#define BWID 80          // bin cols
#define NB (BH*BWID)     // 4800 bins
#define BPT 4            // bins per thread (same bin row)
#define CPG (BWID/BPT)   // 20 col-groups per bin row
#define NTH (BH*CPG)     // 1200 worker threads (bin side)
#define BGRID 5          // 5*256 = 1280 threads >= 1200
#define PSPLIT 118       // pixel-slice CTAs -> 5*118 = 590 CTAs (~4/SM)

#define GDC_WAIT()    asm volatile("griddepcontrol.wait;" ::: "memory")
#define GDC_LAUNCH()  asm volatile("griddepcontrol.launch_dependents;" ::: "memory")

// ---------- device scratch (zero-initialized at module load) ----------
__device__ float4 g_pix[2*NP]; // {px, py, 2ux, 2uy}
__device__ float  g_dd[2*NP];  // dist
__device__ int    g_n[2];      // compacted counts (class 1,2)  -- reset by finish_k
__device__ int    g_cnt[NC];   // raw label counts (incl. cls0) -- reset by finish_k
__device__ float2 g_acc[2*NB]; // {votes, dsum} per bin, class 1,2 -- zeroed by prep_k
__device__ float  g_rois_scratch[NC*6];
__device__ float  g_hough_scratch[NC*NB];

// ---------- kernel 1: zero acc + gather/compact/prune (R12 logic verbatim) ----------
#define PREP_TH (NC*NB)   // 14400 threads; 9600 zero g_acc, 12288 do pixels
__global__ void prep_k(const int* __restrict__ label,
                       const float* __restrict__ vert) {
    int i = blockIdx.x * blockDim.x + threadIdx.x;
    if (i < 2*NB) g_acc[i] = make_float2(0.0f, 0.0f);

    if (i < NP) {   // NP % 256 == 0: warps in here are fully active
        int lane = threadIdx.x & 31;
        unsigned lmlt = (1u << lane) - 1u;

        int r = i / PW, c = i % PW;
        int vy = r * SKIP, vx = c * SKIP;
        int vl = label[vy * WW + vx];

        // warp-aggregated g_cnt: 3 atomics per warp instead of 32
        #pragma unroll
        for (int cl = 0; cl < NC; cl++) {
            unsigned m = __ballot_sync(0xffffffffu, vl == cl);
            if (m && lane == (__ffs(m) - 1))
                atomicAdd(&g_cnt[cl], __popc(m));
        }

        float ux = 0.f, uy = 0.f, dd = 0.f;
        bool want = false;
        if (vl > 0) {
            int base = (vl * 3) * (HH * WW) + vy * WW + vx;
            ux = vert[base];
            uy = vert[base + HH * WW];
            dd = vert[base + 2 * HH * WW];
            // prune: cos = (d.u)/|d| <= |u|; if ux^2+uy^2 <= 0.25, cos>0.5 impossible
            want = fmaf(ux, ux, uy * uy) > 0.25f;
        }

        // warp-aggregated slot allocation
        #pragma unroll
        for (int seg = 0; seg < 2; seg++) {
            bool p = want && (vl == seg + 1);
            unsigned m = __ballot_sync(0xffffffffu, p);
            if (m) {
                int leader = __ffs(m) - 1;
                int base = 0;
                if (lane == leader) base = atomicAdd(&g_n[seg], __popc(m));
                base = __shfl_sync(0xffffffffu, base, leader);
                if (p) {
                    int slot = seg * NP + base + __popc(m & lmlt);
                    g_pix[slot] = make_float4((float)vx, (float)vy, 2.0f * ux, 2.0f * uy);
                    g_dd[slot]  = dd;
                }
            }
        }
    }

    GDC_LAUNCH();   // all stores above are pre-trigger
}

// ---------- kernel 2: pairwise voting (R12 mainloop verbatim; v2 reduction flush) ----------
__global__ void __launch_bounds__(256, 4)
vote_k() {
    __shared__ float4 s_pix[256];
    __shared__ float  s_dd[256];

    int tid = threadIdx.x;
    int gt  = blockIdx.x * 256 + tid;
    bool active = gt < NTH;
    int binrow = gt / CPG;
    int colg   = gt % CPG;
    float byf  = 4.0f + 8.0f * (float)binrow;
    float bx0  = 4.0f + 8.0f * (float)(colg * BPT);

    GDC_WAIT();   // prep_k's writes visible

    for (int seg = 0; seg < 2; seg++) {
        int n     = g_n[seg];
        int chunk = (n + PSPLIT - 1) / PSPLIT;
        int start = blockIdx.y * chunk;
        int end   = min(start + chunk, n);

        float aH[BPT] = {0.f, 0.f, 0.f, 0.f};
        float aD[BPT] = {0.f, 0.f, 0.f, 0.f};

        for (int t = start; t < end; t += 256) {
            int m = min(256, end - t);
            __syncthreads();
            if (tid < m) {
                int s = seg * NP + t + tid;
                s_pix[tid] = g_pix[s];
                s_dd[tid]  = g_dd[s];
            }
            __syncthreads();

            #pragma unroll 4
            for (int j = 0; j < m; j++) {
                float4 P = s_pix[j];                 // one LDS.128 (broadcast)
                float dd = s_dd[j];
                float px = P.x, py = P.y, ux = P.z, uy = P.w;
                float ddy = byf - py;
                float t2  = fmaf(ddy, ddy, 1e-6f);   // ddy^2 + eps
                float dyu = ddy * uy;                // ddy * 2uy
                #pragma unroll
                for (int b = 0; b < BPT; b++) {
                    float ddx = (bx0 + 8.0f * (float)b) - px;
                    float nxy = fmaf(ddx, ddx, t2);   // ddx^2+ddy^2+eps
                    float dot = fmaf(ddx, ux, dyu);   // 2*(ddx*ux+ddy*uy)
                    bool  ok  = (dot > 0.0f) && (dot * dot > nxy);
                    aH[b] += ok ? 1.0f : 0.0f;
                    aD[b] += ok ? dd   : 0.0f;
                }
            }
        }

        if (active) {
            int binbase = binrow * BWID + colg * BPT;
            #pragma unroll
            for (int b = 0; b < BPT; b++) {
                if (aH[b] != 0.0f) {
                    float2* dst = &g_acc[seg * NB + binbase + b];
                    asm volatile("red.global.add.v2.f32 [%0], {%1, %2};"
                                 :: "l"(dst), "f"(aH[b]), "f"(aD[b]) : "memory");
                }
            }
        }
        __syncthreads();
    }

    GDC_LAUNCH();
}

// ---------- kernel 3: write hough + argmax + ROI (3 CTAs, PDL) + counter reset ----------
__global__ void finish_k(float* __restrict__ hough,
                         float* __restrict__ rois,
                         const float* __restrict__ meta,
                         const float* __restrict__ extents) {
    __shared__ float sv[256];
    __shared__ int   si[256];
    int c   = blockIdx.x;
    int tid = threadIdx.x;

    GDC_WAIT();

    int peak = 0; float votes = 0.0f; float ds = 0.0f;
    if (c == 0) {
        // class-0 row is identically zero; just materialize it
        #pragma unroll
        for (int k = 0; k < 19; k++) {
            int i = tid + k * 256;
            if (i < NB) hough[i] = 0.0f;
        }
    } else {
        float best = -1.0f; int bi = 0;
        #pragma unroll
        for (int k = 0; k < 19; k++) {
            int i = tid + k * 256;
            if (i < NB) {
                float2 v = g_acc[(c - 1) * NB + i];
                hough[c * NB + i] = v.x;
                if (v.x > best) { best = v.x; bi = i; }   // ascending i -> first max
            }
        }
        sv[tid] = best; si[tid] = bi;
        __syncthreads();
        #pragma unroll
        for (int s = 128; s > 0; s >>= 1) {
            if (tid < s) {
                float v2 = sv[tid + s]; int i2 = si[tid + s];
                if (v2 > sv[tid] || (v2 == sv[tid] && i2 < si[tid])) {
                    sv[tid] = v2; si[tid] = i2;
                }
            }
            __syncthreads();
        }
        peak = si[0]; votes = sv[0];
        if (tid == 0) ds = g_acc[(c - 1) * NB + peak].y;
    }

    if (tid == 0) {
        float depth = ds / fmaxf(votes, 1.0f);
        float cx = 4.0f + 8.0f * (float)(peak % BWID);
        float cy = 4.0f + 8.0f * (float)(peak / BWID);
        float cnt = (float)g_cnt[c];
        float score = votes / fmaxf(cnt, 1.0f);
        bool  valid = (cnt > 5.0f) && (score > 0.3f);
        float fx = meta[0], fy = meta[4];
        float e0 = extents[c*3+0], e1 = extents[c*3+1], e2 = extents[c*3+2];
        float diag = sqrtf(e0*e0 + e1*e1 + e2*e2);
        float sz = fmaxf(fabsf(depth), 0.001f);
        float bw = fabsf(diag * fx) / sz;
        float bh = fabsf(diag * fy) / sz;
        rois[c*6+0] = (float)c;
        rois[c*6+1] = cx - bw * 0.5f;
        rois[c*6+2] = cy - bh * 0.5f;
        rois[c*6+3] = cx + bw * 0.5f;
        rois[c*6+4] = cy + bh * 0.5f;
        rois[c*6+5] = valid ? score : 0.0f;

        // reset counters for the next graph replay (g_acc re-zeroed by prep_k)
        g_cnt[c] = 0;
        if (c == 0) { g_n[0] = 0; g_n[1] = 0; }
    }
}

extern "C" void kernel_launch(void* const* d_in, const int* in_sizes, int n_in,
                              void* d_out, int out_size) {
    const int*   label = (const int*)  d_in[0];
    const float* vert  = (const float*)d_in[1];
    const float* meta  = (const float*)d_in[2];
    const float* ext   = (const float*)d_in[3];
    float* out = (float*)d_out;

    // Output is the flattened tuple (rois[3,6], hough[3,4800]) -> 18 + 14400.
    float *rois_p, *hough_p;
    if (out_size >= NC*6 + NC*NB) {
        rois_p = out; hough_p = out + NC*6;
    } else if (out_size >= NC*NB) {
        void* tmp = nullptr;
        cudaGetSymbolAddress(&tmp, g_rois_scratch);
        rois_p = (float*)tmp; hough_p = out;
    } else {
        void* tmp = nullptr;
        cudaGetSymbolAddress(&tmp, g_hough_scratch);
        rois_p = out; hough_p = (float*)tmp;
    }

    prep_k<<<(PREP_TH + 255) / 256, 256>>>(label, vert);

    cudaLaunchAttribute pdl[1];
    pdl[0].id = cudaLaunchAttributeProgrammaticStreamSerialization;
    pdl[0].val.programmaticStreamSerializationAllowed = 1;

    {   // vote_k with PDL
        cudaLaunchConfig_t cfg = {};
        cfg.gridDim  = dim3(BGRID, PSPLIT);
        cfg.blockDim = dim3(256);
        cfg.attrs    = pdl;
        cfg.numAttrs = 1;
        cudaLaunchKernelEx(&cfg, vote_k);
    }
    {   // finish_k with PDL
        cudaLaunchConfig_t cfg = {};
        cfg.gridDim  = dim3(NC);
        cfg.blockDim = dim3(256);
        cfg.attrs    = pdl;
        cfg.numAttrs = 1;
        cudaLaunchKernelEx(&cfg, finish_k, hough_p, rois_p, meta, ext);
    }
}

// round 17
// speedup vs baseline: 1.2323x; 1.2323x over previous
#include <cuda_runtime.h>

#define HH 480
#define WW 640
#define NC 3
#define SKIP 5
#define PH 96            // HH/SKIP
#define PW 128           // WW/SKIP
#define NP (PH*PW)       // 12288 sampled pixels
#define BH 60            // bin rows   (GRID=8, start 4)
#define BWID 80          // bin cols
#define NB (BH*BWID)     // 4800 bins
#define BPT 4            // bins per thread (same bin row)
#define CPG (BWID/BPT)   // 20 col-groups per bin row
#define NTH (BH*CPG)     // 1200 worker threads (bin side)
#define BGRID 5          // 5*256 = 1280 threads >= 1200
#define PSPLIT 59        // pixel slices per segment; 5*59*2 = 590 CTAs (occ-4 resident)

#define GDC_WAIT()    asm volatile("griddepcontrol.wait;" ::: "memory")
#define GDC_LAUNCH()  asm volatile("griddepcontrol.launch_dependents;" ::: "memory")

// ---------- device scratch (zero-initialized at module load) ----------
__device__ float4 g_pix[2*NP]; // {px, py, 2ux, 2uy}
__device__ float  g_dd[2*NP];  // dist
__device__ int    g_n[2];      // compacted counts (class 1,2)  -- reset by finish_k
__device__ int    g_cnt[NC];   // raw label counts (incl. cls0) -- reset by finish_k
__device__ float  g_dsum[2*NB];
__device__ float  g_rois_scratch[NC*6];
__device__ float  g_hough_scratch[NC*NB];

// ---------- kernel 1: zero hough/dsum + gather/compact/prune (R12 verbatim) ----------
#define PREP_TH (NC*NB)   // 14400 >= NP
__global__ void prep_k(const int* __restrict__ label,
                       const float* __restrict__ vert,
                       float* __restrict__ hough) {
    int i = blockIdx.x * blockDim.x + threadIdx.x;
    if (i < NC*NB) hough[i] = 0.0f;
    if (i < 2*NB)  g_dsum[i] = 0.0f;

    if (i < NP) {   // NP % 256 == 0: warps in here are fully active
        int lane = threadIdx.x & 31;
        unsigned lmlt = (1u << lane) - 1u;

        int r = i / PW, c = i % PW;
        int vy = r * SKIP, vx = c * SKIP;
        int vl = label[vy * WW + vx];

        // warp-aggregated g_cnt: 3 atomics per warp instead of 32
        #pragma unroll
        for (int cl = 0; cl < NC; cl++) {
            unsigned m = __ballot_sync(0xffffffffu, vl == cl);
            if (m && lane == (__ffs(m) - 1))
                atomicAdd(&g_cnt[cl], __popc(m));
        }

        float ux = 0.f, uy = 0.f, dd = 0.f;
        bool want = false;
        if (vl > 0) {
            int base = (vl * 3) * (HH * WW) + vy * WW + vx;
            ux = vert[base];
            uy = vert[base + HH * WW];
            dd = vert[base + 2 * HH * WW];
            // prune: cos = (d.u)/|d| <= |u|; if ux^2+uy^2 <= 0.25, cos>0.5 impossible
            want = fmaf(ux, ux, uy * uy) > 0.25f;
        }

        // warp-aggregated slot allocation
        #pragma unroll
        for (int seg = 0; seg < 2; seg++) {
            bool p = want && (vl == seg + 1);
            unsigned m = __ballot_sync(0xffffffffu, p);
            if (m) {
                int leader = __ffs(m) - 1;
                int base = 0;
                if (lane == leader) base = atomicAdd(&g_n[seg], __popc(m));
                base = __shfl_sync(0xffffffffu, base, leader);
                if (p) {
                    int slot = seg * NP + base + __popc(m & lmlt);
                    g_pix[slot] = make_float4((float)vx, (float)vy, 2.0f * ux, 2.0f * uy);
                    g_dd[slot]  = dd;
                }
            }
        }
    }

    GDC_LAUNCH();   // all stores above are pre-trigger
}

// ---------- kernel 2: pairwise voting (R12 loop verbatim; segment -> gridDim.z) ----------
__global__ void __launch_bounds__(256, 4)
vote_k(float* __restrict__ hough) {
    __shared__ float4 s_pix[256];
    __shared__ float  s_dd[256];

    int tid = threadIdx.x;
    int gt  = blockIdx.x * 256 + tid;
    bool active = gt < NTH;
    int binrow = gt / CPG;
    int colg   = gt % CPG;
    float byf  = 4.0f + 8.0f * (float)binrow;
    float bx0  = 4.0f + 8.0f * (float)(colg * BPT);
    int seg    = blockIdx.z;                 // one segment per CTA

    GDC_WAIT();   // prep_k's writes visible

    {
        int n     = g_n[seg];
        int chunk = (n + PSPLIT - 1) / PSPLIT;
        int start = blockIdx.y * chunk;
        int end   = min(start + chunk, n);

        float aH[BPT] = {0.f, 0.f, 0.f, 0.f};
        float aD[BPT] = {0.f, 0.f, 0.f, 0.f};

        for (int t = start; t < end; t += 256) {
            int m = min(256, end - t);
            __syncthreads();
            if (tid < m) {
                int s = seg * NP + t + tid;
                s_pix[tid] = g_pix[s];
                s_dd[tid]  = g_dd[s];
            }
            __syncthreads();

            #pragma unroll 4
            for (int j = 0; j < m; j++) {
                float4 P = s_pix[j];                 // one LDS.128 (broadcast)
                float dd = s_dd[j];
                float px = P.x, py = P.y, ux = P.z, uy = P.w;
                float ddy = byf - py;
                float t2  = fmaf(ddy, ddy, 1e-6f);   // ddy^2 + eps
                float dyu = ddy * uy;                // ddy * 2uy
                #pragma unroll
                for (int b = 0; b < BPT; b++) {
                    float ddx = (bx0 + 8.0f * (float)b) - px;
                    float nxy = fmaf(ddx, ddx, t2);   // ddx^2+ddy^2+eps
                    float dot = fmaf(ddx, ux, dyu);   // 2*(ddx*ux+ddy*uy)
                    bool  ok  = (dot > 0.0f) && (dot * dot > nxy);
                    aH[b] += ok ? 1.0f : 0.0f;
                    aD[b] += ok ? dd   : 0.0f;
                }
            }
        }

        if (active) {
            int binbase = binrow * BWID + colg * BPT;
            #pragma unroll
            for (int b = 0; b < BPT; b++) {
                if (aH[b] != 0.0f) {
                    atomicAdd(&hough[(seg + 1) * NB + binbase + b], aH[b]);
                    atomicAdd(&g_dsum[seg * NB + binbase + b], aD[b]);
                }
            }
        }
    }

    GDC_LAUNCH();
}

// ---------- kernel 3: argmax + ROI epilogue (3 CTAs, PDL) + counter reset ----------
__global__ void finish_k(const float* __restrict__ hough,
                         float* __restrict__ rois,
                         const float* __restrict__ meta,
                         const float* __restrict__ extents) {
    __shared__ float sv[256];
    __shared__ int   si[256];
    int c   = blockIdx.x;
    int tid = threadIdx.x;

    GDC_WAIT();

    if (c > 0) {
        float best = -1.0f; int bi = 0;
        #pragma unroll
        for (int k = 0; k < 19; k++) {
            int i = tid + k * 256;
            float v = (i < NB) ? hough[c * NB + i] : -2.0f;
            if (v > best) { best = v; bi = i; }   // ascending i -> first max kept
        }
        sv[tid] = best; si[tid] = bi;
        __syncthreads();
        #pragma unroll
        for (int s = 128; s > 0; s >>= 1) {
            if (tid < s) {
                float v2 = sv[tid + s]; int i2 = si[tid + s];
                if (v2 > sv[tid] || (v2 == sv[tid] && i2 < si[tid])) {
                    sv[tid] = v2; si[tid] = i2;
                }
            }
            __syncthreads();
        }
    }

    if (tid == 0) {
        int peak; float votes;
        if (c == 0) { peak = 0; votes = 0.0f; }   // class-0 hough row is identically 0
        else        { peak = si[0]; votes = sv[0]; }
        float ds    = (c > 0) ? g_dsum[(c - 1) * NB + peak] : 0.0f;
        float depth = ds / fmaxf(votes, 1.0f);
        float cx = 4.0f + 8.0f * (float)(peak % BWID);
        float cy = 4.0f + 8.0f * (float)(peak / BWID);
        float cnt = (float)g_cnt[c];
        float score = votes / fmaxf(cnt, 1.0f);
        bool  valid = (cnt > 5.0f) && (score > 0.3f);
        float fx = meta[0], fy = meta[4];
        float e0 = extents[c*3+0], e1 = extents[c*3+1], e2 = extents[c*3+2];
        float diag = sqrtf(e0*e0 + e1*e1 + e2*e2);
        float sz = fmaxf(fabsf(depth), 0.001f);
        float bw = fabsf(diag * fx) / sz;
        float bh = fabsf(diag * fy) / sz;
        rois[c*6+0] = (float)c;
        rois[c*6+1] = cx - bw * 0.5f;
        rois[c*6+2] = cy - bh * 0.5f;
        rois[c*6+3] = cx + bw * 0.5f;
        rois[c*6+4] = cy + bh * 0.5f;
        rois[c*6+5] = valid ? score : 0.0f;

        // reset counters for the next graph replay
        g_cnt[c] = 0;
        if (c == 0) { g_n[0] = 0; g_n[1] = 0; }
    }
}

extern "C" void kernel_launch(void* const* d_in, const int* in_sizes, int n_in,
                              void* d_out, int out_size) {
    const int*   label = (const int*)  d_in[0];
    const float* vert  = (const float*)d_in[1];
    const float* meta  = (const float*)d_in[2];
    const float* ext   = (const float*)d_in[3];
    float* out = (float*)d_out;

    // Output is the flattened tuple (rois[3,6], hough[3,4800]) -> 18 + 14400.
    float *rois_p, *hough_p;
    if (out_size >= NC*6 + NC*NB) {
        rois_p = out; hough_p = out + NC*6;
    } else if (out_size >= NC*NB) {
        void* tmp = nullptr;
        cudaGetSymbolAddress(&tmp, g_rois_scratch);
        rois_p = (float*)tmp; hough_p = out;
    } else {
        void* tmp = nullptr;
        cudaGetSymbolAddress(&tmp, g_hough_scratch);
        rois_p = out; hough_p = (float*)tmp;
    }

    prep_k<<<(PREP_TH + 255) / 256, 256>>>(label, vert, hough_p);

    cudaLaunchAttribute pdl[1];
    pdl[0].id = cudaLaunchAttributeProgrammaticStreamSerialization;
    pdl[0].val.programmaticStreamSerializationAllowed = 1;

    {   // vote_k with PDL: grid (5, 59, 2) = 590 CTAs
        cudaLaunchConfig_t cfg = {};
        cfg.gridDim  = dim3(BGRID, PSPLIT, 2);
        cfg.blockDim = dim3(256);
        cfg.attrs    = pdl;
        cfg.numAttrs = 1;
        cudaLaunchKernelEx(&cfg, vote_k, hough_p);
    }
    {   // finish_k with PDL
        cudaLaunchConfig_t cfg = {};
        cfg.gridDim  = dim3(NC);
        cfg.blockDim = dim3(256);
        cfg.attrs    = pdl;
        cfg.numAttrs = 1;
        cudaLaunchKernelEx(&cfg, finish_k, (const float*)hough_p, rois_p, meta, ext);
    }
}